// round 9
// baseline (speedup 1.0000x reference)
#include <cuda_runtime.h>
#include <cuda_fp16.h>
#include <cstdint>

// Problem constants
#define NVEC   32768
#define DIM    256
#define NCODE  4096

// Output layout (all fp32): [quantize 8388608][diff 1][ind 32768]
#define Q_ELEMS   (NVEC * DIM)
#define DIFF_OFF  Q_ELEMS
#define IND_OFF   (Q_ELEMS + 1)

#define NCAND  8
#define MTILE  64

// Scratch
__device__ float  g_embedT[NCODE * DIM];             // [code][dim] fp32
__device__ __align__(16) int8_t g_Bq[NCODE * DIM];   // [code][dim] int8 codes
__device__ float  g_sB[NCODE];                       // per-code step (max/127)
__device__ float  g_enorm[NCODE];
__device__ int    g_cand[NVEC * NCAND];
__device__ double g_part[8192];

// ---------------------------------------------------------------------------
__device__ __forceinline__ uint32_t smem_u32(const void* p) {
    uint32_t a;
    asm("{ .reg .u64 t; cvta.to.shared.u64 t, %1; cvt.u32.u64 %0, t; }"
        : "=r"(a) : "l"(p));
    return a;
}
__device__ __forceinline__ void ldsm_x4(uint32_t r[4], uint32_t addr) {
    asm volatile("ldmatrix.sync.aligned.m8n8.x4.shared.b16 {%0,%1,%2,%3}, [%4];"
                 : "=r"(r[0]), "=r"(r[1]), "=r"(r[2]), "=r"(r[3]) : "r"(addr));
}
__device__ __forceinline__ void mma_s8(int c[4], const uint32_t a[4],
                                       const uint32_t b0, const uint32_t b1) {
    asm volatile(
        "mma.sync.aligned.m16n8k32.row.col.s32.s8.s8.s32 "
        "{%0,%1,%2,%3}, {%4,%5,%6,%7}, {%8,%9}, {%0,%1,%2,%3};"
        : "+r"(c[0]), "+r"(c[1]), "+r"(c[2]), "+r"(c[3])
        : "r"(a[0]), "r"(a[1]), "r"(a[2]), "r"(a[3]), "r"(b0), "r"(b1));
}
#define CP_ASYNC16(dst, src) \
    asm volatile("cp.async.cg.shared.global [%0], [%1], 16;" \
                 :: "r"(dst), "l"(src) : "memory")
#define CP_COMMIT()  asm volatile("cp.async.commit_group;" ::: "memory")
#define CP_WAIT2()   asm volatile("cp.async.wait_group 2;" ::: "memory")

// ---------------------------------------------------------------------------
// SMEM (bytes): A int8 resident 64 rows x 272B (256 data + 16 pad: stride
// == 16 mod 128 -> conflict-free ldmatrix). B: 4 bufs of 128 codes x 48B rows.
#define A_ROW_B   272
#define B_BASE    17408            // 64*272
#define B_ROW_B   48
#define B_BUF_B   6144             // 128*48
#define SMAX_OFF  (B_BASE + 4 * B_BUF_B)   // 41984: 64 int (row maxabs bits)
#define SAINV_OFF (SMAX_OFF + 256)         // 42240: 64 float (row step)
#define SMEM_TOT  (SAINV_OFF + 256)        // 42496 -> 3 CTAs/SM

// ===========================================================================
// int8 IMMA GEMM + per-thread top-3 + merged top-8.
// Grid 512 (64 rows/CTA), block 256 (8 warps: 4m x 2n, warp tile 16x64).
// ===========================================================================
__global__ __launch_bounds__(256, 3)
void vq_mma_kernel(const float* __restrict__ x) {
    extern __shared__ char smem[];
    const uint32_t sb = smem_u32(smem);
    const int t    = threadIdx.x;
    const int wid  = t >> 5, lane = t & 31;
    const int n0   = blockIdx.x * MTILE;
    const int mwarp = (wid & 3) * 16;
    const int nwarp = (wid >> 2) * 64;

    int*   smax  = (int*)(smem + SMAX_OFF);
    float* sAinv = (float*)(smem + SAINV_OFF);

    // ---- pass 1: per-row maxabs ---------------------------------------------
    if (t < 64) smax[t] = 0;
    __syncthreads();
    const float4* xg4 = (const float4*)(x + (size_t)n0 * DIM);
#pragma unroll
    for (int i = 0; i < 16; i++) {
        const int f   = t + i * 256;          // 0..4095 float4
        const int row = f >> 6;
        float4 v = xg4[f];
        float m = fmaxf(fmaxf(fabsf(v.x), fabsf(v.y)),
                        fmaxf(fabsf(v.z), fabsf(v.w)));
        atomicMax(&smax[row], __float_as_int(m));   // m >= 0: int cmp valid
    }
    __syncthreads();
    if (t < 64) {
        float m = __int_as_float(smax[t]);
        sAinv[t] = m * (1.f / 127.f);
    }
    __syncthreads();

    // ---- pass 2: quantize A to int8 in smem ---------------------------------
#pragma unroll
    for (int i = 0; i < 16; i++) {
        const int f   = t + i * 256;
        const int row = f >> 6;
        const int c4  = f & 63;
        float m = __int_as_float(smax[row]);
        float s = (m > 0.f) ? 127.f / m : 0.f;
        float4 v = xg4[f];
        int qx = __float2int_rn(v.x * s);
        int qy = __float2int_rn(v.y * s);
        int qz = __float2int_rn(v.z * s);
        int qw = __float2int_rn(v.w * s);
        char4 c;
        c.x = (char)max(-127, min(127, qx));
        c.y = (char)max(-127, min(127, qy));
        c.z = (char)max(-127, min(127, qz));
        c.w = (char)max(-127, min(127, qw));
        *(char4*)(smem + row * A_ROW_B + c4 * 4) = c;
    }

    // epilogue scales for this thread's two rows
    const float sA0 = sAinv[mwarp + (lane >> 2)];
    const float sA1 = sAinv[mwarp + 8 + (lane >> 2)];

    const uint32_t aBase = sb + (uint32_t)(mwarp + (lane & 15)) * A_ROW_B
                         + (uint32_t)(((lane >> 4) & 1) * 16);
    const uint32_t bBase = sb + B_BASE
                         + (uint32_t)(nwarp + (lane & 7) + ((lane >> 4) & 1) * 8) * B_ROW_B
                         + (uint32_t)(((lane >> 3) & 1) * 16);

    // B chunk (128 codes x 32 k int8, 4KB): 256 x 16B, 1 per thread
    auto issueB = [&](int ch) {
        const int nb = (ch >> 3) * 128;
        const int kb = (ch & 7) * 32;
        const uint32_t bufb = sb + B_BASE + (uint32_t)(ch & 3) * B_BUF_B;
        const int r = t >> 1;
        const int h = t & 1;
        const uint32_t dst = bufb + (uint32_t)r * B_ROW_B + (uint32_t)h * 16;
        const int8_t* srcp = g_Bq + (size_t)(nb + r) * DIM + kb + h * 16;
        CP_ASYNC16(dst, srcp);
    };

    int acc[8][4];
#pragma unroll
    for (int nt = 0; nt < 8; nt++)
#pragma unroll
        for (int q = 0; q < 4; q++) acc[nt][q] = 0;

    // per-thread top-3 per row-slot (2 slots)
    float t3v[2][3];
    int   t3i[2][3];
#pragma unroll
    for (int q = 0; q < 2; q++) {
        t3v[q][0] = 3.4e38f; t3v[q][1] = 3.4e38f; t3v[q][2] = 3.4e38f;
        t3i[q][0] = 0; t3i[q][1] = 1; t3i[q][2] = 2;
    }

    __syncthreads();   // A int8 tile visible to all warps
    issueB(0); CP_COMMIT();
    issueB(1); CP_COMMIT();
    issueB(2); CP_COMMIT();

    const float2* en2 = (const float2*)g_enorm;
    const float2* sb2 = (const float2*)g_sB;

    for (int i = 0; i < 256; i++) {
        CP_WAIT2();
        __syncthreads();

        if (i + 3 < 256) issueB(i + 3);
        CP_COMMIT();

        const uint32_t bufb = (uint32_t)(i & 3) * B_BUF_B;

        uint32_t ah[4];
        ldsm_x4(ah, aBase + (uint32_t)((i & 7) * 32));
        uint32_t bh[8][2];
#pragma unroll
        for (int np = 0; np < 4; np++) {
            uint32_t r[4];
            ldsm_x4(r, bBase + bufb + (uint32_t)np * (16 * B_ROW_B));
            bh[np * 2][0] = r[0]; bh[np * 2][1] = r[1];
            bh[np * 2 + 1][0] = r[2]; bh[np * 2 + 1][1] = r[3];
        }
#pragma unroll
        for (int nt = 0; nt < 8; nt++)
            mma_s8(acc[nt], ah, bh[nt][0], bh[nt][1]);

        if ((i & 7) == 7) {
            const int cbase = (i >> 3) * 128;
#pragma unroll
            for (int nt = 0; nt < 8; nt++) {
                const int j0 = cbase + nwarp + nt * 8 + (lane & 3) * 2;
                const float2 en = __ldg(&en2[j0 >> 1]);
                const float2 sbv = __ldg(&sb2[j0 >> 1]);
                const float f0 = 2.f * sA0 * sbv.x, f1 = 2.f * sA0 * sbv.y;
                const float f2 = 2.f * sA1 * sbv.x, f3 = 2.f * sA1 * sbv.y;
                float d[4];
                d[0] = en.x - f0 * (float)acc[nt][0];
                d[1] = en.y - f1 * (float)acc[nt][1];
                d[2] = en.x - f2 * (float)acc[nt][2];
                d[3] = en.y - f3 * (float)acc[nt][3];
                const int jj[4] = {j0, j0 + 1, j0, j0 + 1};
#pragma unroll
                for (int u = 0; u < 4; u++) {
                    const int q = u >> 1;            // row-slot
                    const float v = d[u];
                    if (v < t3v[q][2]) {
                        if (v < t3v[q][1]) {
                            t3v[q][2] = t3v[q][1]; t3i[q][2] = t3i[q][1];
                            if (v < t3v[q][0]) {
                                t3v[q][1] = t3v[q][0]; t3i[q][1] = t3i[q][0];
                                t3v[q][0] = v;         t3i[q][0] = jj[u];
                            } else {
                                t3v[q][1] = v; t3i[q][1] = jj[u];
                            }
                        } else {
                            t3v[q][2] = v; t3i[q][2] = jj[u];
                        }
                    }
                }
                acc[nt][0] = 0; acc[nt][1] = 0;
                acc[nt][2] = 0; acc[nt][3] = 0;
            }
        }
    }

    // ---- merge: dump per-(lane-group, n-half) top-3, pick top-8 ------------
    __syncthreads();              // all mma/ldmatrix smem reads done
    float* sV = (float*)smem;                 // [64 rows][8 src][3]
    int*   sI = (int*)(smem + 64 * 8 * 3 * 4);
    const int src = (wid >> 2) * 4 + (lane & 3);
#pragma unroll
    for (int q = 0; q < 2; q++) {
        const int row = mwarp + q * 8 + (lane >> 2);
        const int base = (row * 8 + src) * 3;
#pragma unroll
        for (int e = 0; e < 3; e++) {
            sV[base + e] = t3v[q][e];
            sI[base + e] = t3i[q][e];
        }
    }
    __syncthreads();
    if (t < MTILE) {
        float v8[NCAND];
        int   i8[NCAND];
#pragma unroll
        for (int c = 0; c < NCAND; c++) { v8[c] = 3.4e38f; i8[c] = c; }
        const int base = t * 24;
        for (int e = 0; e < 24; e++) {
            float v = sV[base + e];
            int   id = sI[base + e];
            if (v < v8[NCAND - 1]) {
                int p = NCAND - 1;
                while (p > 0 && v < v8[p - 1]) {
                    v8[p] = v8[p - 1]; i8[p] = i8[p - 1]; p--;
                }
                v8[p] = v; i8[p] = id;
            }
        }
        const int n = n0 + t;
#pragma unroll
        for (int c = 0; c < NCAND; c++) g_cand[n * NCAND + c] = i8[c];
    }
}

// ===========================================================================
// Prep kernels
// ===========================================================================
__global__ void enorm_kernel(const float* __restrict__ embed) {
    int j = blockIdx.x * blockDim.x + threadIdx.x;
    float s = 0.f;
#pragma unroll 8
    for (int d = 0; d < DIM; d++) {
        float v = embed[d * NCODE + j];
        s += v * v;
    }
    g_enorm[j] = s;
}

__global__ void transpose_kernel(const float* __restrict__ embed) {
    __shared__ float tile[32][33];
    int j0 = blockIdx.x * 32;
    int d0 = blockIdx.y * 32;
    int tx = threadIdx.x, ty = threadIdx.y;  // 32 x 8
#pragma unroll
    for (int i = 0; i < 4; i++)
        tile[ty + i * 8][tx] = embed[(size_t)(d0 + ty + i * 8) * NCODE + j0 + tx];
    __syncthreads();
#pragma unroll
    for (int i = 0; i < 4; i++)
        g_embedT[(size_t)(j0 + ty + i * 8) * DIM + d0 + tx] = tile[tx][ty + i * 8];
}

// per-code int8 quantization: one warp per code
__global__ void quantB_kernel() {
    const int gw = (blockIdx.x * blockDim.x + threadIdx.x) >> 5;
    const int lane = threadIdx.x & 31;
    if (gw >= NCODE) return;
    const float* e = g_embedT + (size_t)gw * DIM;
    float v[8];
    float m = 0.f;
#pragma unroll
    for (int i = 0; i < 8; i++) {
        v[i] = e[lane * 8 + i];
        m = fmaxf(m, fabsf(v[i]));
    }
#pragma unroll
    for (int off = 16; off; off >>= 1)
        m = fmaxf(m, __shfl_xor_sync(0xffffffffu, m, off));
    float s = (m > 0.f) ? 127.f / m : 0.f;
    char q[8];
#pragma unroll
    for (int i = 0; i < 8; i++) {
        int qi = __float2int_rn(v[i] * s);
        q[i] = (char)max(-127, min(127, qi));
    }
    *(uint2*)(g_Bq + (size_t)gw * DIM + lane * 8) = *(uint2*)q;
    if (lane == 0) g_sB[gw] = m * (1.f / 127.f);
}

// ===========================================================================
// Exact rescore (sequential k-order fp32 — validated rounding order) over 8
// candidates + gather + diff. One warp per row, 4 warps per block.
// ===========================================================================
__global__ __launch_bounds__(128)
void rescore_gather_kernel(const float* __restrict__ input,
                           float* __restrict__ out) {
    __shared__ float xs[4][256];
    __shared__ float es[4][NCAND][257];
    __shared__ double ws[4];

    const int wid = threadIdx.x >> 5, lane = threadIdx.x & 31;
    const int n = blockIdx.x * 4 + wid;

    int cand[NCAND];
#pragma unroll
    for (int c = 0; c < NCAND; c++) cand[c] = g_cand[n * NCAND + c];

    const float4* x4 = (const float4*)(input + (size_t)n * DIM);
    float4 v0 = x4[lane], v1 = x4[lane + 32];
    *(float4*)&xs[wid][lane * 4]       = v0;
    *(float4*)&xs[wid][128 + lane * 4] = v1;
#pragma unroll
    for (int c = 0; c < NCAND; c++) {
        const float4* e4 = (const float4*)(g_embedT + (size_t)cand[c] * DIM);
        float4 a = e4[lane], b = e4[lane + 32];
        es[wid][c][lane * 4 + 0] = a.x; es[wid][c][lane * 4 + 1] = a.y;
        es[wid][c][lane * 4 + 2] = a.z; es[wid][c][lane * 4 + 3] = a.w;
        es[wid][c][128 + lane * 4 + 0] = b.x; es[wid][c][128 + lane * 4 + 1] = b.y;
        es[wid][c][128 + lane * 4 + 2] = b.z; es[wid][c][128 + lane * 4 + 3] = b.w;
    }
    __syncwarp();

    float dist = 3.4e38f;
    int   cidx = 0x7fffffff;
    if (lane < NCAND) {
        float dot = 0.f;
#pragma unroll 8
        for (int k = 0; k < 256; k++)
            dot += xs[wid][k] * es[wid][lane][k];
        float en = __ldg(&g_enorm[cand[lane]]);
        dist = en - 2.0f * dot;
        cidx = cand[lane];
    }
    float bv = dist; int bi = cidx; int bslot = lane;
#pragma unroll
    for (int l = 0; l < NCAND; l++) {
        float ov = __shfl_sync(0xffffffffu, dist, l);
        int   oi = __shfl_sync(0xffffffffu, cidx, l);
        if (ov < bv || (ov == bv && oi < bi)) { bv = ov; bi = oi; bslot = l; }
    }
    const int w    = __shfl_sync(0xffffffffu, bslot, 0);
    const int widx = __shfl_sync(0xffffffffu, bi, 0);

    float4 oa, ob;
    oa.x = es[wid][w][lane * 4 + 0]; oa.y = es[wid][w][lane * 4 + 1];
    oa.z = es[wid][w][lane * 4 + 2]; oa.w = es[wid][w][lane * 4 + 3];
    ob.x = es[wid][w][128 + lane * 4 + 0]; ob.y = es[wid][w][128 + lane * 4 + 1];
    ob.z = es[wid][w][128 + lane * 4 + 2]; ob.w = es[wid][w][128 + lane * 4 + 3];

    float4* o4 = (float4*)(out + (size_t)n * DIM);
    o4[lane]      = oa;
    o4[lane + 32] = ob;
    if (lane == 0)
        out[IND_OFF + n] = (float)widx;

    float dx0 = oa.x - v0.x, dx1 = oa.y - v0.y, dx2 = oa.z - v0.z, dx3 = oa.w - v0.w;
    float dy0 = ob.x - v1.x, dy1 = ob.y - v1.y, dy2 = ob.z - v1.z, dy3 = ob.w - v1.w;
    float s = dx0 * dx0 + dx1 * dx1 + dx2 * dx2 + dx3 * dx3
            + dy0 * dy0 + dy1 * dy1 + dy2 * dy2 + dy3 * dy3;
    double sd = (double)s;
#pragma unroll
    for (int off = 16; off; off >>= 1)
        sd += __shfl_xor_sync(0xffffffffu, sd, off);
    if (lane == 0) ws[wid] = sd;
    __syncthreads();
    if (threadIdx.x == 0) {
        double tot = 0.0;
#pragma unroll
        for (int i = 0; i < 4; i++) tot += ws[i];
        g_part[blockIdx.x] = tot;
    }
}

__global__ void diff_kernel(float* __restrict__ out) {
    __shared__ double s[128];
    int t = threadIdx.x;
    double a = 0.0;
    for (int i = 0; i < 64; i++) a += g_part[t + i * 128];
    s[t] = a;
    __syncthreads();
    if (t == 0) {
        double tot = 0.0;
        for (int i = 0; i < 128; i++) tot += s[i];
        out[DIFF_OFF] = (float)(tot / (double)Q_ELEMS);
    }
}

// ===========================================================================
extern "C" void kernel_launch(void* const* d_in, const int* in_sizes, int n_in,
                              void* d_out, int out_size) {
    const float* input = (const float*)d_in[0];   // [8,64,64,256]
    const float* embed = (const float*)d_in[1];   // [256,4096]
    float* out = (float*)d_out;

    enorm_kernel<<<NCODE / 256, 256>>>(embed);
    transpose_kernel<<<dim3(NCODE / 32, DIM / 32), dim3(32, 8)>>>(embed);
    quantB_kernel<<<NCODE / 8, 256>>>();

    cudaFuncSetAttribute(vq_mma_kernel,
                         cudaFuncAttributeMaxDynamicSharedMemorySize, SMEM_TOT);
    vq_mma_kernel<<<NVEC / MTILE, 256, SMEM_TOT>>>(input);

    rescore_gather_kernel<<<NVEC / 4, 128>>>(input, out);
    diff_kernel<<<1, 128>>>(out);
}

// round 10
// speedup vs baseline: 1.6266x; 1.6266x over previous
#include <cuda_runtime.h>
#include <cuda_fp16.h>
#include <cstdint>

// Problem constants
#define NVEC   32768
#define DIM    256
#define NCODE  4096

// Output layout (all fp32): [quantize 8388608][diff 1][ind 32768]
#define Q_ELEMS   (NVEC * DIM)
#define DIFF_OFF  Q_ELEMS
#define IND_OFF   (Q_ELEMS + 1)

#define NCAND  8
#define MTILE  64

// Scratch
__device__ float  g_embedT[NCODE * DIM];            // [code][dim] fp32
__device__ __align__(16) __half g_Bh[NCODE * DIM];  // [code][dim] fp16 codes
__device__ float  g_enorm[NCODE];
__device__ int    g_cand[NVEC * NCAND];
__device__ double g_part[8192];

// ---------------------------------------------------------------------------
__device__ __forceinline__ uint32_t smem_u32(const void* p) {
    uint32_t a;
    asm("{ .reg .u64 t; cvta.to.shared.u64 t, %1; cvt.u32.u64 %0, t; }"
        : "=r"(a) : "l"(p));
    return a;
}
__device__ __forceinline__ void ldsm_x4(uint32_t r[4], uint32_t addr) {
    asm volatile("ldmatrix.sync.aligned.m8n8.x4.shared.b16 {%0,%1,%2,%3}, [%4];"
                 : "=r"(r[0]), "=r"(r[1]), "=r"(r[2]), "=r"(r[3]) : "r"(addr));
}
__device__ __forceinline__ void mma_f16(float c[4], const uint32_t a[4],
                                        const uint32_t b0, const uint32_t b1) {
    asm volatile(
        "mma.sync.aligned.m16n8k16.row.col.f32.f16.f16.f32 "
        "{%0,%1,%2,%3}, {%4,%5,%6,%7}, {%8,%9}, {%0,%1,%2,%3};"
        : "+f"(c[0]), "+f"(c[1]), "+f"(c[2]), "+f"(c[3])
        : "r"(a[0]), "r"(a[1]), "r"(a[2]), "r"(a[3]), "r"(b0), "r"(b1));
}
#define CP_ASYNC16(dst, src) \
    asm volatile("cp.async.cg.shared.global [%0], [%1], 16;" \
                 :: "r"(dst), "l"(src) : "memory")
#define CP_COMMIT()  asm volatile("cp.async.commit_group;" ::: "memory")
#define CP_WAIT2()   asm volatile("cp.async.wait_group 2;" ::: "memory")

// ---------------------------------------------------------------------------
// SMEM: A resident (64 x 264 halves, 528B rows, fp16 only); B: 4 bufs of
// 128 codes x 32 k fp16 (80B rows). Total 74752 B -> 3 CTAs/SM.
#define A_ROW_B   528
#define A_BYTES   33792            // 64*528
#define B_BASE    33792
#define B_ROW_B   80
#define B_BUF_B   10240            // 128*80
#define SMEM_TOT  (B_BASE + 4 * B_BUF_B)   // 74752

// ===========================================================================
// Single-product fp16 mma GEMM + per-thread top-3 + merged top-8.
// Grid 512 (64 rows/CTA), block 256 (8 warps: 4m x 2n, warp tile 16x64).
// OCC 3: 24 warps/SM to hide barrier + cp.async gaps in the tensor stream.
// ===========================================================================
__global__ __launch_bounds__(256, 3)
void vq_mma_kernel(const float* __restrict__ x) {
    extern __shared__ char smem[];
    const uint32_t sb = smem_u32(smem);
    const int t    = threadIdx.x;
    const int wid  = t >> 5, lane = t & 31;
    const int n0   = blockIdx.x * MTILE;
    const int mwarp = (wid & 3) * 16;
    const int nwarp = (wid >> 2) * 64;

    // ---- convert A (64 x rows) to fp16 in smem ----------------------------
    {
        const float4* xg4 = (const float4*)(x + (size_t)n0 * DIM);
#pragma unroll
        for (int i = 0; i < 16; i++) {
            const int f   = t + i * 256;          // 0..4095 float4
            const int row = f >> 6;
            const int c4  = f & 63;
            float4 v = xg4[f];
            __half hx = __float2half_rn(v.x), hy = __float2half_rn(v.y);
            __half hz = __float2half_rn(v.z), hw = __float2half_rn(v.w);
            const int off = row * A_ROW_B + c4 * 8;
            *(__half2*)(smem + off)     = __halves2half2(hx, hy);
            *(__half2*)(smem + off + 4) = __halves2half2(hz, hw);
        }
    }

    const uint32_t aBase = sb + (uint32_t)(mwarp + (lane & 15)) * A_ROW_B
                         + (uint32_t)(((lane >> 4) & 1) * 8) * 2;
    const uint32_t bBase = sb + B_BASE
                         + (uint32_t)(nwarp + (lane & 7) + ((lane >> 4) & 1) * 8) * B_ROW_B
                         + (uint32_t)(((lane >> 3) & 1) * 8) * 2;

    // B chunk (128 codes x 32 k fp16, 8KB): 512 x 16B
    auto issueB = [&](int ch) {
        const int nb = (ch >> 3) * 128;
        const int kb = (ch & 7) * 32;
        const uint32_t bufb = sb + B_BASE + (uint32_t)(ch & 3) * B_BUF_B;
#pragma unroll
        for (int j = 0; j < 2; j++) {
            const int s = t + j * 256;           // 0..511
            const int r = s >> 2;
            const int q = s & 3;
            const uint32_t dst = bufb + (uint32_t)r * B_ROW_B + (uint32_t)q * 16;
            const __half* srcp = g_Bh + (size_t)(nb + r) * DIM + kb + q * 8;
            CP_ASYNC16(dst, srcp);
        }
    };

    float acc[8][4];
#pragma unroll
    for (int nt = 0; nt < 8; nt++)
#pragma unroll
        for (int q = 0; q < 4; q++) acc[nt][q] = 0.f;

    // per-thread top-3 per row-slot (2 slots: rows lane>>2 and +8)
    float t3v[2][3];
    int   t3i[2][3];
#pragma unroll
    for (int q = 0; q < 2; q++) {
        t3v[q][0] = 3.4e38f; t3v[q][1] = 3.4e38f; t3v[q][2] = 3.4e38f;
        t3i[q][0] = 0; t3i[q][1] = 1; t3i[q][2] = 2;
    }

    issueB(0); CP_COMMIT();
    issueB(1); CP_COMMIT();
    issueB(2); CP_COMMIT();

    const float2* en2 = (const float2*)g_enorm;

    for (int i = 0; i < 256; i++) {
        CP_WAIT2();
        __syncthreads();

        if (i + 3 < 256) issueB(i + 3);
        CP_COMMIT();

        const uint32_t bufb = (uint32_t)(i & 3) * B_BUF_B;
        const uint32_t kcb  = (uint32_t)(i & 7) * 32;

#pragma unroll
        for (int kk = 0; kk < 2; kk++) {
            const uint32_t kab = (kcb + kk * 16) * 2;
            uint32_t ah[4];
            ldsm_x4(ah, aBase + kab);
            uint32_t bh[8][2];
#pragma unroll
            for (int np = 0; np < 4; np++) {
                uint32_t r[4];
                ldsm_x4(r, bBase + bufb + (uint32_t)np * (16 * B_ROW_B) + (uint32_t)kk * 32);
                bh[np * 2][0] = r[0]; bh[np * 2][1] = r[1];
                bh[np * 2 + 1][0] = r[2]; bh[np * 2 + 1][1] = r[3];
            }
#pragma unroll
            for (int nt = 0; nt < 8; nt++)
                mma_f16(acc[nt], ah, bh[nt][0], bh[nt][1]);
        }

        if ((i & 7) == 7) {
            const int cbase = (i >> 3) * 128;
#pragma unroll
            for (int nt = 0; nt < 8; nt++) {
                const int j0 = cbase + nwarp + nt * 8 + (lane & 3) * 2;
                const float2 en = __ldg(&en2[j0 >> 1]);
                float d[4];
                d[0] = fmaf(-2.f, acc[nt][0], en.x);
                d[1] = fmaf(-2.f, acc[nt][1], en.y);
                d[2] = fmaf(-2.f, acc[nt][2], en.x);
                d[3] = fmaf(-2.f, acc[nt][3], en.y);
                const int jj[4] = {j0, j0 + 1, j0, j0 + 1};
#pragma unroll
                for (int u = 0; u < 4; u++) {
                    const int q = u >> 1;            // row-slot
                    const float v = d[u];
                    if (v < t3v[q][2]) {
                        if (v < t3v[q][1]) {
                            t3v[q][2] = t3v[q][1]; t3i[q][2] = t3i[q][1];
                            if (v < t3v[q][0]) {
                                t3v[q][1] = t3v[q][0]; t3i[q][1] = t3i[q][0];
                                t3v[q][0] = v;         t3i[q][0] = jj[u];
                            } else {
                                t3v[q][1] = v; t3i[q][1] = jj[u];
                            }
                        } else {
                            t3v[q][2] = v; t3i[q][2] = jj[u];
                        }
                    }
                }
                acc[nt][0] = 0.f; acc[nt][1] = 0.f;
                acc[nt][2] = 0.f; acc[nt][3] = 0.f;
            }
        }
    }

    // ---- merge: dump per-(lane-group, n-half) top-3, pick top-8 ------------
    __syncthreads();              // all mma/ldmatrix smem reads done
    float* sV = (float*)smem;                 // [64 rows][8 src][3]
    int*   sI = (int*)(smem + 64 * 8 * 3 * 4);
    const int src = (wid >> 2) * 4 + (lane & 3);
#pragma unroll
    for (int q = 0; q < 2; q++) {
        const int row = mwarp + q * 8 + (lane >> 2);
        const int base = (row * 8 + src) * 3;
#pragma unroll
        for (int e = 0; e < 3; e++) {
            sV[base + e] = t3v[q][e];
            sI[base + e] = t3i[q][e];
        }
    }
    __syncthreads();
    if (t < MTILE) {
        float v8[NCAND];
        int   i8[NCAND];
#pragma unroll
        for (int c = 0; c < NCAND; c++) { v8[c] = 3.4e38f; i8[c] = c; }
        const int base = t * 24;
        for (int e = 0; e < 24; e++) {
            float v = sV[base + e];
            int   id = sI[base + e];
            if (v < v8[NCAND - 1]) {
                int p = NCAND - 1;
                while (p > 0 && v < v8[p - 1]) {
                    v8[p] = v8[p - 1]; i8[p] = i8[p - 1]; p--;
                }
                v8[p] = v; i8[p] = id;
            }
        }
        const int n = n0 + t;
#pragma unroll
        for (int c = 0; c < NCAND; c++) g_cand[n * NCAND + c] = i8[c];
    }
}

// ===========================================================================
// Prep kernels
// ===========================================================================
__global__ void enorm_kernel(const float* __restrict__ embed) {
    int j = blockIdx.x * blockDim.x + threadIdx.x;
    float s = 0.f;
#pragma unroll 8
    for (int d = 0; d < DIM; d++) {
        float v = embed[d * NCODE + j];
        s += v * v;
    }
    g_enorm[j] = s;
}

__global__ void transpose_split_kernel(const float* __restrict__ embed) {
    __shared__ float tile[32][33];
    int j0 = blockIdx.x * 32;
    int d0 = blockIdx.y * 32;
    int tx = threadIdx.x, ty = threadIdx.y;  // 32 x 8
#pragma unroll
    for (int i = 0; i < 4; i++)
        tile[ty + i * 8][tx] = embed[(size_t)(d0 + ty + i * 8) * NCODE + j0 + tx];
    __syncthreads();
#pragma unroll
    for (int i = 0; i < 4; i++) {
        float v = tile[tx][ty + i * 8];
        size_t o = (size_t)(j0 + ty + i * 8) * DIM + d0 + tx;
        g_embedT[o] = v;
        g_Bh[o] = __float2half_rn(v);
    }
}

// ===========================================================================
// Exact rescore (sequential k-order fp32 — validated rounding order) over 8
// candidates + gather + diff. One warp per row, 4 warps per block.
// ===========================================================================
__global__ __launch_bounds__(128)
void rescore_gather_kernel(const float* __restrict__ input,
                           float* __restrict__ out) {
    __shared__ float xs[4][256];
    __shared__ float es[4][NCAND][257];
    __shared__ double ws[4];

    const int wid = threadIdx.x >> 5, lane = threadIdx.x & 31;
    const int n = blockIdx.x * 4 + wid;

    int cand[NCAND];
#pragma unroll
    for (int c = 0; c < NCAND; c++) cand[c] = g_cand[n * NCAND + c];

    const float4* x4 = (const float4*)(input + (size_t)n * DIM);
    float4 v0 = x4[lane], v1 = x4[lane + 32];
    *(float4*)&xs[wid][lane * 4]       = v0;
    *(float4*)&xs[wid][128 + lane * 4] = v1;
#pragma unroll
    for (int c = 0; c < NCAND; c++) {
        const float4* e4 = (const float4*)(g_embedT + (size_t)cand[c] * DIM);
        float4 a = e4[lane], b = e4[lane + 32];
        es[wid][c][lane * 4 + 0] = a.x; es[wid][c][lane * 4 + 1] = a.y;
        es[wid][c][lane * 4 + 2] = a.z; es[wid][c][lane * 4 + 3] = a.w;
        es[wid][c][128 + lane * 4 + 0] = b.x; es[wid][c][128 + lane * 4 + 1] = b.y;
        es[wid][c][128 + lane * 4 + 2] = b.z; es[wid][c][128 + lane * 4 + 3] = b.w;
    }
    __syncwarp();

    float dist = 3.4e38f;
    int   cidx = 0x7fffffff;
    if (lane < NCAND) {
        float dot = 0.f;
#pragma unroll 8
        for (int k = 0; k < 256; k++)
            dot += xs[wid][k] * es[wid][lane][k];
        float en = __ldg(&g_enorm[cand[lane]]);
        dist = en - 2.0f * dot;
        cidx = cand[lane];
    }
    float bv = dist; int bi = cidx; int bslot = lane;
#pragma unroll
    for (int l = 0; l < NCAND; l++) {
        float ov = __shfl_sync(0xffffffffu, dist, l);
        int   oi = __shfl_sync(0xffffffffu, cidx, l);
        if (ov < bv || (ov == bv && oi < bi)) { bv = ov; bi = oi; bslot = l; }
    }
    const int w    = __shfl_sync(0xffffffffu, bslot, 0);
    const int widx = __shfl_sync(0xffffffffu, bi, 0);

    float4 oa, ob;
    oa.x = es[wid][w][lane * 4 + 0]; oa.y = es[wid][w][lane * 4 + 1];
    oa.z = es[wid][w][lane * 4 + 2]; oa.w = es[wid][w][lane * 4 + 3];
    ob.x = es[wid][w][128 + lane * 4 + 0]; ob.y = es[wid][w][128 + lane * 4 + 1];
    ob.z = es[wid][w][128 + lane * 4 + 2]; ob.w = es[wid][w][128 + lane * 4 + 3];

    float4* o4 = (float4*)(out + (size_t)n * DIM);
    o4[lane]      = oa;
    o4[lane + 32] = ob;
    if (lane == 0)
        out[IND_OFF + n] = (float)widx;

    float dx0 = oa.x - v0.x, dx1 = oa.y - v0.y, dx2 = oa.z - v0.z, dx3 = oa.w - v0.w;
    float dy0 = ob.x - v1.x, dy1 = ob.y - v1.y, dy2 = ob.z - v1.z, dy3 = ob.w - v1.w;
    float s = dx0 * dx0 + dx1 * dx1 + dx2 * dx2 + dx3 * dx3
            + dy0 * dy0 + dy1 * dy1 + dy2 * dy2 + dy3 * dy3;
    double sd = (double)s;
#pragma unroll
    for (int off = 16; off; off >>= 1)
        sd += __shfl_xor_sync(0xffffffffu, sd, off);
    if (lane == 0) ws[wid] = sd;
    __syncthreads();
    if (threadIdx.x == 0) {
        double tot = 0.0;
#pragma unroll
        for (int i = 0; i < 4; i++) tot += ws[i];
        g_part[blockIdx.x] = tot;
    }
}

__global__ void diff_kernel(float* __restrict__ out) {
    __shared__ double s[128];
    int t = threadIdx.x;
    double a = 0.0;
    for (int i = 0; i < 64; i++) a += g_part[t + i * 128];
    s[t] = a;
    __syncthreads();
    if (t == 0) {
        double tot = 0.0;
        for (int i = 0; i < 128; i++) tot += s[i];
        out[DIFF_OFF] = (float)(tot / (double)Q_ELEMS);
    }
}

// ===========================================================================
extern "C" void kernel_launch(void* const* d_in, const int* in_sizes, int n_in,
                              void* d_out, int out_size) {
    const float* input = (const float*)d_in[0];   // [8,64,64,256]
    const float* embed = (const float*)d_in[1];   // [256,4096]
    float* out = (float*)d_out;

    enorm_kernel<<<NCODE / 256, 256>>>(embed);
    transpose_split_kernel<<<dim3(NCODE / 32, DIM / 32), dim3(32, 8)>>>(embed);

    cudaFuncSetAttribute(vq_mma_kernel,
                         cudaFuncAttributeMaxDynamicSharedMemorySize, SMEM_TOT);
    vq_mma_kernel<<<NVEC / MTILE, 256, SMEM_TOT>>>(input);

    rescore_gather_kernel<<<NVEC / 4, 128>>>(input, out);
    diff_kernel<<<1, 128>>>(out);
}